// round 12
// baseline (speedup 1.0000x reference)
#include <cuda_runtime.h>
#include <cuda_fp16.h>
#include <cstdint>

#define BATCH 2
#define SEQ   2048
#define DIMC  1024
#define NHEAD 16
#define HD    64
#define SCALE 0.125f            // 64^-0.5
#define SC2   (0.125f * 1.44269504089f)   // SCALE * log2(e)

#define M_TOT (BATCH*SEQ)       // 4096
#define QKV_N (3*DIMC)          // 3072

// fp16 scratch (allocation-free rule: __device__ globals)
__device__ __half g_xh [(size_t)M_TOT * DIMC];
__device__ __half g_wqh[(size_t)QKV_N * DIMC];
__device__ __half g_wph[(size_t)DIMC * DIMC];
__device__ __half g_qh [(size_t)M_TOT * QKV_N];
__device__ __half g_aoh[(size_t)M_TOT * DIMC];

// ===========================================================================
// Primitives
// ===========================================================================
__device__ __forceinline__ uint32_t smem_u32(const void* p) {
    uint32_t a;
    asm("{ .reg .u64 t; cvta.to.shared.u64 t, %1; cvt.u32.u64 %0, t; }" : "=r"(a) : "l"(p));
    return a;
}
__device__ __forceinline__ void ldsm_x4(uint32_t* r, uint32_t addr) {
    asm volatile("ldmatrix.sync.aligned.m8n8.x4.shared.b16 {%0,%1,%2,%3}, [%4];"
        : "=r"(r[0]), "=r"(r[1]), "=r"(r[2]), "=r"(r[3]) : "r"(addr));
}
__device__ __forceinline__ void ldsm_x4_t(uint32_t* r, uint32_t addr) {
    asm volatile("ldmatrix.sync.aligned.m8n8.x4.trans.shared.b16 {%0,%1,%2,%3}, [%4];"
        : "=r"(r[0]), "=r"(r[1]), "=r"(r[2]), "=r"(r[3]) : "r"(addr));
}
// D(16x8 f32) += A(16x16 f16) * B(16x8 f16, col)
__device__ __forceinline__ void mma_f16(float* d, const uint32_t* a, uint32_t b0, uint32_t b1) {
    asm volatile(
        "mma.sync.aligned.m16n8k16.row.col.f32.f16.f16.f32 "
        "{%0,%1,%2,%3}, {%4,%5,%6,%7}, {%8,%9}, {%0,%1,%2,%3};"
        : "+f"(d[0]), "+f"(d[1]), "+f"(d[2]), "+f"(d[3])
        : "r"(a[0]), "r"(a[1]), "r"(a[2]), "r"(a[3]), "r"(b0), "r"(b1));
}
__device__ __forceinline__ uint32_t packh(float lo, float hi) {
    __half2 t = __floats2half2_rn(lo, hi);
    return *reinterpret_cast<uint32_t*>(&t);
}
#define CP16(dst, src) \
    asm volatile("cp.async.cg.shared.global [%0], [%1], 16;" \
        :: "r"(dst), "l"(__cvta_generic_to_global(src)) : "memory")
#define CP_COMMIT() asm volatile("cp.async.commit_group;" ::: "memory")
#define CP_WAIT0()  asm volatile("cp.async.wait_group 0;" ::: "memory")
#define CP_WAIT1()  asm volatile("cp.async.wait_group 1;" ::: "memory")

// ===========================================================================
// Fused convert prepass: fp32 -> fp16 over 3 segments (one launch)
// ===========================================================================
__global__ __launch_bounds__(256) void cvt16_all(
    const float* __restrict__ x,  __half* __restrict__ xh,
    const float* __restrict__ wq, __half* __restrict__ wqh,
    const float* __restrict__ wp, __half* __restrict__ wph)
{
    const float* in;  __half* out;  int n;
    if (blockIdx.y == 0)      { in = x;  out = xh;  n = M_TOT * DIMC; }
    else if (blockIdx.y == 1) { in = wq; out = wqh; n = QKV_N * DIMC; }
    else                      { in = wp; out = wph; n = DIMC * DIMC; }
    int i = (blockIdx.x * 256 + threadIdx.x) * 4;
    if (i >= n) return;
    float4 v = *(const float4*)(in + i);
    *(uint2*)(out + i) = make_uint2(packh(v.x, v.y), packh(v.z, v.w));
}

// ===========================================================================
// fp16 GEMM-NT, cp.async 3-stage pipeline, K-chunk 64, 2 CTAs/SM.
// (unchanged from R11 passing kernel)
// ===========================================================================
#define CHK    64
#define TILEK  16384                     // 128 rows x 128 bytes
#define STG_B  (2 * TILEK)               // A, B = 32KB
#define NSTG   3
#define GEMM_SMEM (NSTG * STG_B)         // 98304 B

__global__ __launch_bounds__(256, 2) void gemm_half(
    const __half* __restrict__ Ah, const __half* __restrict__ Bh,
    float* __restrict__ C, __half* __restrict__ Ch,
    int M, int N, int K)
{
    extern __shared__ char smem[];
    const uint32_t sbase = smem_u32(smem);
    const int tid  = threadIdx.x;
    const int wid  = tid >> 5;
    const int lane = tid & 31;
    const int bm = blockIdx.y * 128;
    const int bn = blockIdx.x * 128;

    const int warpM = (wid & 1) * 64;
    const int warpN = (wid >> 1) * 32;
    const int lrow = lane & 15;
    const int kb   = (lane >> 4) * 16;

    uint32_t aRow[4], aSwz[4];
#pragma unroll
    for (int mi = 0; mi < 4; mi++) {
        int r = warpM + mi * 16 + lrow;
        aRow[mi] = (uint32_t)(r * 128);
        aSwz[mi] = (uint32_t)((r & 7) << 4);
    }
    uint32_t bRow[2], bSwz[2];
#pragma unroll
    for (int nj = 0; nj < 2; nj++) {
        int r = warpN + nj * 16 + lrow;
        bRow[nj] = (uint32_t)(r * 128);
        bSwz[nj] = (uint32_t)((r & 7) << 4);
    }

    const int crow = tid >> 1;
    const int chalf = tid & 1;
    uint32_t stC[4];
#pragma unroll
    for (int j = 0; j < 4; j++) {
        uint32_t off = (uint32_t)(crow * 128 + (chalf * 4 + j) * 16);
        stC[j] = off ^ ((off >> 3) & 0x70);
    }
    const size_t aoff = (size_t)(bm + crow) * K + chalf * 32;
    const size_t boff = (size_t)(bn + crow) * K + chalf * 32;

    float acc[4][4][4];
#pragma unroll
    for (int mi = 0; mi < 4; mi++)
#pragma unroll
        for (int nj = 0; nj < 4; nj++)
#pragma unroll
            for (int k = 0; k < 4; k++) acc[mi][nj][k] = 0.f;

    const int nch = K / CHK;

#pragma unroll
    for (int p = 0; p < NSTG - 1; p++) {
        const uint32_t s = sbase + (uint32_t)p * STG_B;
        const size_t ka = aoff + (size_t)p * CHK;
        const size_t kbo = boff + (size_t)p * CHK;
#pragma unroll
        for (int j = 0; j < 4; j++) {
            CP16(s + 0*TILEK + stC[j], Ah + ka + j * 8);
            CP16(s + 1*TILEK + stC[j], Bh + kbo + j * 8);
        }
        CP_COMMIT();
    }

    for (int ch = 0; ch < nch; ch++) {
        if (ch + 1 < nch) CP_WAIT1(); else CP_WAIT0();
        __syncthreads();

        if (ch + 2 < nch) {
            const uint32_t s = sbase + (uint32_t)((ch + 2) % NSTG) * STG_B;
            const size_t ka = aoff + (size_t)(ch + 2) * CHK;
            const size_t kbo = boff + (size_t)(ch + 2) * CHK;
#pragma unroll
            for (int j = 0; j < 4; j++) {
                CP16(s + 0*TILEK + stC[j], Ah + ka + j * 8);
                CP16(s + 1*TILEK + stC[j], Bh + kbo + j * 8);
            }
            CP_COMMIT();
        }

        const uint32_t bufb = sbase + (uint32_t)(ch % NSTG) * STG_B;
#pragma unroll
        for (int ks = 0; ks < 4; ks++) {
            const uint32_t koff = (uint32_t)(ks * 32 + kb);
            uint32_t ah[4][4], bh[2][4];
#pragma unroll
            for (int mi = 0; mi < 4; mi++)
                ldsm_x4(ah[mi], bufb + 0*TILEK + aRow[mi] + (koff ^ aSwz[mi]));
#pragma unroll
            for (int nj = 0; nj < 2; nj++)
                ldsm_x4(bh[nj], bufb + 1*TILEK + bRow[nj] + (koff ^ bSwz[nj]));
#pragma unroll
            for (int mi = 0; mi < 4; mi++)
#pragma unroll
                for (int nj = 0; nj < 4; nj++)
                    mma_f16(acc[mi][nj], ah[mi], bh[nj>>1][nj&1], bh[nj>>1][(nj&1)+2]);
        }
    }

    const int er = lane >> 2;
    const int ec = (lane & 3) * 2;
    if (C) {
#pragma unroll
        for (int mi = 0; mi < 4; mi++) {
            const int r0 = bm + warpM + mi * 16 + er;
#pragma unroll
            for (int nj = 0; nj < 4; nj++) {
                const int c = bn + warpN + nj * 8 + ec;
                *(float2*)&C[(size_t)r0 * N + c]       = make_float2(acc[mi][nj][0], acc[mi][nj][1]);
                *(float2*)&C[(size_t)(r0 + 8) * N + c] = make_float2(acc[mi][nj][2], acc[mi][nj][3]);
            }
        }
    } else {
#pragma unroll
        for (int mi = 0; mi < 4; mi++) {
            const int r0 = bm + warpM + mi * 16 + er;
#pragma unroll
            for (int nj = 0; nj < 4; nj++) {
                const int c = bn + warpN + nj * 8 + ec;
                *(uint32_t*)&Ch[(size_t)r0 * N + c]       = packh(acc[mi][nj][0], acc[mi][nj][1]);
                *(uint32_t*)&Ch[(size_t)(r0 + 8) * N + c] = packh(acc[mi][nj][2], acc[mi][nj][3]);
            }
        }
    }
}

// ===========================================================================
// fp16 flash attention, BQ=64, BK=64, 128 threads (4 warps), 4 CTAs/SM,
// 3-stage cp.async pipeline. exp2-domain softmax.
// ===========================================================================
#define FA_NSTG 3
#define FA_STG  16384                    // KH 8KB + VH 8KB
#define FA_SMEM (FA_NSTG * FA_STG)       // 49152 B

__global__ __launch_bounds__(128, 4) void flash_half(
    const __half* __restrict__ qh_g, const float* __restrict__ head_w,
    __half* __restrict__ aoh)
{
    extern __shared__ char smem[];
    const uint32_t sb = smem_u32(smem);

    const int tid  = threadIdx.x;
    const int wid  = tid >> 5;           // 0..3
    const int lane = tid & 31;
    const int q0 = blockIdx.x * 64;
    const int h  = blockIdx.y;
    const int b  = blockIdx.z;

    float hw;
    {
        float mx = -1e30f;
#pragma unroll
        for (int i = 0; i < NHEAD; i++) mx = fmaxf(mx, head_w[i]);
        float ssum = 0.f;
#pragma unroll
        for (int i = 0; i < NHEAD; i++) ssum += __expf(head_w[i] - mx);
        hw = __expf(head_w[h] - mx) / ssum;
    }

    // staging geometry (128 thr, 64 rows x 128B tile): row tid>>1, half tid&1
    const int crow = tid >> 1;
    const int chalf = tid & 1;
    uint32_t stC[4];
#pragma unroll
    for (int j = 0; j < 4; j++) {
        uint32_t off = (uint32_t)(crow * 128 + (chalf * 4 + j) * 16);
        stC[j] = off ^ ((off >> 3) & 0x70);
    }

    // ---- stage Q (fp16, 8KB -> stage 0), read fragments ----
    {
        const size_t qoff = (size_t)(b * SEQ + q0 + crow) * 3 * DIMC + h * HD + chalf * 32;
#pragma unroll
        for (int j = 0; j < 4; j++)
            CP16(sb + stC[j], qh_g + qoff + j * 8);
        CP_COMMIT();
        CP_WAIT0();
        __syncthreads();
    }

    const int lrow = lane & 15;
    const int kb   = (lane >> 4) * 16;
    uint32_t qh[4][4];
    {
        const uint32_t aOff = (uint32_t)((wid * 16 + lrow) * 128);
        const uint32_t aSwz = (uint32_t)((lrow & 7) << 4);
#pragma unroll
        for (int ks = 0; ks < 4; ks++) {
            const uint32_t koff = (uint32_t)(ks * 32 + kb);
            ldsm_x4(qh[ks], sb + aOff + (koff ^ aSwz));
        }
    }
    __syncthreads();   // Q fully read before KV staging overwrites stage 0

    const size_t kvbase = (size_t)(b * SEQ + crow) * 3 * DIMC + h * HD + chalf * 32;
    const size_t kstep  = (size_t)64 * 3 * DIMC;   // 64 seq rows per tile

    const int ntl = SEQ / 64;            // 32 tiles

    // prologue: KV tiles 0, 1
#pragma unroll
    for (int p = 0; p < FA_NSTG - 1; p++) {
        const uint32_t s = sb + (uint32_t)p * FA_STG;
        const size_t kt_ = kvbase + (size_t)p * kstep + (size_t)1 * DIMC;
        const size_t vt_ = kvbase + (size_t)p * kstep + (size_t)2 * DIMC;
#pragma unroll
        for (int j = 0; j < 4; j++) {
            CP16(s + 0*8192 + stC[j], qh_g + kt_ + j * 8);
            CP16(s + 1*8192 + stC[j], qh_g + vt_ + j * 8);
        }
        CP_COMMIT();
    }

    uint32_t bOff[4];
#pragma unroll
    for (int g = 0; g < 4; g++) bOff[g] = (uint32_t)((g * 16 + lrow) * 128);
    const uint32_t bSwz = (uint32_t)((lrow & 7) << 4);
    const uint32_t vRowBase = (uint32_t)(lane & 15);
    const uint32_t vColPart = (uint32_t)((lane >> 4) * 16);

    float m_r[2] = {-1e30f, -1e30f};     // in exp2 (scaled) domain
    float l_r[2] = {0.f, 0.f};
    float o[8][4];
#pragma unroll
    for (int g = 0; g < 8; g++)
#pragma unroll
        for (int e = 0; e < 4; e++) o[g][e] = 0.f;

    for (int kt = 0; kt < ntl; kt++) {
        if (kt + 1 < ntl) CP_WAIT1(); else CP_WAIT0();
        __syncthreads();

        if (kt + FA_NSTG - 1 < ntl) {
            const uint32_t s = sb + (uint32_t)((kt + FA_NSTG - 1) % FA_NSTG) * FA_STG;
            const size_t kt_ = kvbase + (size_t)(kt + FA_NSTG - 1) * kstep + (size_t)1 * DIMC;
            const size_t vt_ = kvbase + (size_t)(kt + FA_NSTG - 1) * kstep + (size_t)2 * DIMC;
#pragma unroll
            for (int j = 0; j < 4; j++) {
                CP16(s + 0*8192 + stC[j], qh_g + kt_ + j * 8);
                CP16(s + 1*8192 + stC[j], qh_g + vt_ + j * 8);
            }
            CP_COMMIT();
        }

        const uint32_t sKH = sb + (uint32_t)(kt % FA_NSTG) * FA_STG;
        const uint32_t sVH = sKH + 8192;

        // ---- S = Q K^T (fp16): 16 q-rows x 64 keys per warp ----
        float s[8][4];
#pragma unroll
        for (int nj = 0; nj < 8; nj++)
#pragma unroll
            for (int e = 0; e < 4; e++) s[nj][e] = 0.f;

#pragma unroll
        for (int ks = 0; ks < 4; ks++) {
            const uint32_t koff = (uint32_t)(ks * 32 + kb);
#pragma unroll
            for (int g = 0; g < 4; g++) {
                uint32_t kh4[4];
                ldsm_x4(kh4, sKH + bOff[g] + (koff ^ bSwz));
                mma_f16(s[2*g],   qh[ks], kh4[0], kh4[2]);
                mma_f16(s[2*g+1], qh[ks], kh4[1], kh4[3]);
            }
        }

        // ---- online softmax (exp2 domain: s scaled by SCALE*log2e) ----
        float mx0 = -1e30f, mx1 = -1e30f;
#pragma unroll
        for (int nj = 0; nj < 8; nj++) {
            s[nj][0] *= SC2; s[nj][1] *= SC2; s[nj][2] *= SC2; s[nj][3] *= SC2;
            mx0 = fmaxf(mx0, fmaxf(s[nj][0], s[nj][1]));
            mx1 = fmaxf(mx1, fmaxf(s[nj][2], s[nj][3]));
        }
        mx0 = fmaxf(mx0, __shfl_xor_sync(0xffffffffu, mx0, 1));
        mx0 = fmaxf(mx0, __shfl_xor_sync(0xffffffffu, mx0, 2));
        mx1 = fmaxf(mx1, __shfl_xor_sync(0xffffffffu, mx1, 1));
        mx1 = fmaxf(mx1, __shfl_xor_sync(0xffffffffu, mx1, 2));
        const float mn0 = fmaxf(m_r[0], mx0);
        const float mn1 = fmaxf(m_r[1], mx1);
        const float alpha0 = exp2f(m_r[0] - mn0);
        const float alpha1 = exp2f(m_r[1] - mn1);
        m_r[0] = mn0; m_r[1] = mn1;
        float sum0 = 0.f, sum1 = 0.f;
#pragma unroll
        for (int nj = 0; nj < 8; nj++) {
            s[nj][0] = exp2f(s[nj][0] - mn0); sum0 += s[nj][0];
            s[nj][1] = exp2f(s[nj][1] - mn0); sum0 += s[nj][1];
            s[nj][2] = exp2f(s[nj][2] - mn1); sum1 += s[nj][2];
            s[nj][3] = exp2f(s[nj][3] - mn1); sum1 += s[nj][3];
        }
        sum0 += __shfl_xor_sync(0xffffffffu, sum0, 1);
        sum0 += __shfl_xor_sync(0xffffffffu, sum0, 2);
        sum1 += __shfl_xor_sync(0xffffffffu, sum1, 1);
        sum1 += __shfl_xor_sync(0xffffffffu, sum1, 2);
        l_r[0] = l_r[0] * alpha0 + sum0;
        l_r[1] = l_r[1] * alpha1 + sum1;
#pragma unroll
        for (int g = 0; g < 8; g++) {
            o[g][0] *= alpha0; o[g][1] *= alpha0;
            o[g][2] *= alpha1; o[g][3] *= alpha1;
        }

        // ---- P fragments (fp16) ----
        uint32_t pa[4][4];
#pragma unroll
        for (int t = 0; t < 4; t++) {
            pa[t][0] = packh(s[2*t][0], s[2*t][1]);
            pa[t][1] = packh(s[2*t][2], s[2*t][3]);
            pa[t][2] = packh(s[2*t+1][0], s[2*t+1][1]);
            pa[t][3] = packh(s[2*t+1][2], s[2*t+1][3]);
        }

        // ---- O += P V (fp16) ----
#pragma unroll
        for (int t = 0; t < 4; t++) {
#pragma unroll
            for (int g = 0; g < 4; g++) {
                const uint32_t vr = (uint32_t)(16 * t) + vRowBase;
                const uint32_t vc = (uint32_t)(g * 32) + vColPart;
                const uint32_t voff = vr * 128 + (vc ^ ((vr & 7) << 4));
                uint32_t vh4[4];
                ldsm_x4_t(vh4, sVH + voff);
                mma_f16(o[2*g],   pa[t], vh4[0], vh4[1]);
                mma_f16(o[2*g+1], pa[t], vh4[2], vh4[3]);
            }
        }
    }

    // ---- epilogue: O/l * hw -> fp16 ao ----
    const int er = lane >> 2;
    const int ec = (lane & 3) * 2;
    const float inv0 = hw / l_r[0];
    const float inv1 = hw / l_r[1];
    const int r0 = q0 + wid * 16 + er;
#pragma unroll
    for (int g = 0; g < 8; g++) {
        const int d = h * HD + g * 8 + ec;
        const size_t i0 = (size_t)(b * SEQ + r0) * DIMC + d;
        const size_t i1 = (size_t)(b * SEQ + r0 + 8) * DIMC + d;
        *(uint32_t*)&aoh[i0] = packh(o[g][0] * inv0, o[g][1] * inv0);
        *(uint32_t*)&aoh[i1] = packh(o[g][2] * inv1, o[g][3] * inv1);
    }
}

// ===========================================================================
extern "C" void kernel_launch(void* const* d_in, const int* in_sizes, int n_in,
                              void* d_out, int out_size)
{
    const float* x      = (const float*)d_in[0];
    const float* w_qkv  = (const float*)d_in[1];
    const float* w_proj = (const float*)d_in[2];
    const float* head_w = (const float*)d_in[3];
    float* out = (float*)d_out;

    __half *xh, *wqh, *wph, *qh, *aoh;
    cudaGetSymbolAddress((void**)&xh,  g_xh);
    cudaGetSymbolAddress((void**)&wqh, g_wqh);
    cudaGetSymbolAddress((void**)&wph, g_wph);
    cudaGetSymbolAddress((void**)&qh,  g_qh);
    cudaGetSymbolAddress((void**)&aoh, g_aoh);

    cudaFuncSetAttribute(gemm_half, cudaFuncAttributeMaxDynamicSharedMemorySize, GEMM_SMEM);
    cudaFuncSetAttribute(flash_half, cudaFuncAttributeMaxDynamicSharedMemorySize, FA_SMEM);

    // 0) fused convert prepass (x, w_qkv, w_proj -> fp16) in ONE launch
    {
        dim3 g0((M_TOT * DIMC) / 1024, 3);
        cvt16_all<<<g0, 256>>>(x, xh, w_qkv, wqh, w_proj, wph);
    }

    // 1) QKV projection -> fp16 qkv
    dim3 g1(QKV_N / 128, M_TOT / 128);
    gemm_half<<<g1, 256, GEMM_SMEM>>>(xh, wqh, nullptr, qh, M_TOT, QKV_N, DIMC);

    // 2) flash attention + head weights -> fp16 ao  (BQ=64, 128 thr, 4 CTAs/SM)
    dim3 g2(SEQ / 64, NHEAD, BATCH);
    flash_half<<<g2, 128, FA_SMEM>>>(qh, head_w, aoh);

    // 3) output projection -> fp32 out
    dim3 g3(DIMC / 128, M_TOT / 128);
    gemm_half<<<g3, 256, GEMM_SMEM>>>(aoh, wph, out, nullptr, M_TOT, DIMC, DIMC);
}

// round 13
// speedup vs baseline: 1.0373x; 1.0373x over previous
#include <cuda_runtime.h>
#include <cuda_fp16.h>
#include <cstdint>

#define BATCH 2
#define SEQ   2048
#define DIMC  1024
#define NHEAD 16
#define HD    64
#define SCALE 0.125f            // 64^-0.5
#define SC2   (0.125f * 1.44269504089f)   // SCALE * log2(e)

#define M_TOT (BATCH*SEQ)       // 4096
#define QKV_N (3*DIMC)          // 3072

// fp16 scratch (allocation-free rule: __device__ globals)
__device__ __half g_xh [(size_t)M_TOT * DIMC];
__device__ __half g_wqh[(size_t)QKV_N * DIMC];
__device__ __half g_wph[(size_t)DIMC * DIMC];
__device__ __half g_qh [(size_t)M_TOT * QKV_N];
__device__ __half g_aoh[(size_t)M_TOT * DIMC];

// ===========================================================================
// Primitives
// ===========================================================================
__device__ __forceinline__ uint32_t smem_u32(const void* p) {
    uint32_t a;
    asm("{ .reg .u64 t; cvta.to.shared.u64 t, %1; cvt.u32.u64 %0, t; }" : "=r"(a) : "l"(p));
    return a;
}
__device__ __forceinline__ void ldsm_x4(uint32_t* r, uint32_t addr) {
    asm volatile("ldmatrix.sync.aligned.m8n8.x4.shared.b16 {%0,%1,%2,%3}, [%4];"
        : "=r"(r[0]), "=r"(r[1]), "=r"(r[2]), "=r"(r[3]) : "r"(addr));
}
__device__ __forceinline__ void ldsm_x4_t(uint32_t* r, uint32_t addr) {
    asm volatile("ldmatrix.sync.aligned.m8n8.x4.trans.shared.b16 {%0,%1,%2,%3}, [%4];"
        : "=r"(r[0]), "=r"(r[1]), "=r"(r[2]), "=r"(r[3]) : "r"(addr));
}
// D(16x8 f32) += A(16x16 f16) * B(16x8 f16, col)
__device__ __forceinline__ void mma_f16(float* d, const uint32_t* a, uint32_t b0, uint32_t b1) {
    asm volatile(
        "mma.sync.aligned.m16n8k16.row.col.f32.f16.f16.f32 "
        "{%0,%1,%2,%3}, {%4,%5,%6,%7}, {%8,%9}, {%0,%1,%2,%3};"
        : "+f"(d[0]), "+f"(d[1]), "+f"(d[2]), "+f"(d[3])
        : "r"(a[0]), "r"(a[1]), "r"(a[2]), "r"(a[3]), "r"(b0), "r"(b1));
}
__device__ __forceinline__ uint32_t packh(float lo, float hi) {
    __half2 t = __floats2half2_rn(lo, hi);
    return *reinterpret_cast<uint32_t*>(&t);
}
#define CP16(dst, src) \
    asm volatile("cp.async.cg.shared.global [%0], [%1], 16;" \
        :: "r"(dst), "l"(__cvta_generic_to_global(src)) : "memory")
#define CP_COMMIT() asm volatile("cp.async.commit_group;" ::: "memory")
#define CP_WAIT0()  asm volatile("cp.async.wait_group 0;" ::: "memory")
#define CP_WAIT1()  asm volatile("cp.async.wait_group 1;" ::: "memory")
#define CP_WAIT2()  asm volatile("cp.async.wait_group 2;" ::: "memory")

// ===========================================================================
// Fused convert prepass: fp32 -> fp16 over 3 segments (one launch)
// ===========================================================================
__global__ __launch_bounds__(256) void cvt16_all(
    const float* __restrict__ x,  __half* __restrict__ xh,
    const float* __restrict__ wq, __half* __restrict__ wqh,
    const float* __restrict__ wp, __half* __restrict__ wph)
{
    const float* in;  __half* out;  int n;
    if (blockIdx.y == 0)      { in = x;  out = xh;  n = M_TOT * DIMC; }
    else if (blockIdx.y == 1) { in = wq; out = wqh; n = QKV_N * DIMC; }
    else                      { in = wp; out = wph; n = DIMC * DIMC; }
    int i = (blockIdx.x * 256 + threadIdx.x) * 4;
    if (i >= n) return;
    float4 v = *(const float4*)(in + i);
    *(uint2*)(out + i) = make_uint2(packh(v.x, v.y), packh(v.z, v.w));
}

// ===========================================================================
// fp16 GEMM-NT, cp.async 3-stage pipeline, K-chunk 64, 2 CTAs/SM.
// (unchanged from R11 passing kernel)
// ===========================================================================
#define CHK    64
#define TILEK  16384                     // 128 rows x 128 bytes
#define STG_B  (2 * TILEK)               // A, B = 32KB
#define NSTG   3
#define GEMM_SMEM (NSTG * STG_B)         // 98304 B

__global__ __launch_bounds__(256, 2) void gemm_half(
    const __half* __restrict__ Ah, const __half* __restrict__ Bh,
    float* __restrict__ C, __half* __restrict__ Ch,
    int M, int N, int K)
{
    extern __shared__ char smem[];
    const uint32_t sbase = smem_u32(smem);
    const int tid  = threadIdx.x;
    const int wid  = tid >> 5;
    const int lane = tid & 31;
    const int bm = blockIdx.y * 128;
    const int bn = blockIdx.x * 128;

    const int warpM = (wid & 1) * 64;
    const int warpN = (wid >> 1) * 32;
    const int lrow = lane & 15;
    const int kb   = (lane >> 4) * 16;

    uint32_t aRow[4], aSwz[4];
#pragma unroll
    for (int mi = 0; mi < 4; mi++) {
        int r = warpM + mi * 16 + lrow;
        aRow[mi] = (uint32_t)(r * 128);
        aSwz[mi] = (uint32_t)((r & 7) << 4);
    }
    uint32_t bRow[2], bSwz[2];
#pragma unroll
    for (int nj = 0; nj < 2; nj++) {
        int r = warpN + nj * 16 + lrow;
        bRow[nj] = (uint32_t)(r * 128);
        bSwz[nj] = (uint32_t)((r & 7) << 4);
    }

    const int crow = tid >> 1;
    const int chalf = tid & 1;
    uint32_t stC[4];
#pragma unroll
    for (int j = 0; j < 4; j++) {
        uint32_t off = (uint32_t)(crow * 128 + (chalf * 4 + j) * 16);
        stC[j] = off ^ ((off >> 3) & 0x70);
    }
    const size_t aoff = (size_t)(bm + crow) * K + chalf * 32;
    const size_t boff = (size_t)(bn + crow) * K + chalf * 32;

    float acc[4][4][4];
#pragma unroll
    for (int mi = 0; mi < 4; mi++)
#pragma unroll
        for (int nj = 0; nj < 4; nj++)
#pragma unroll
            for (int k = 0; k < 4; k++) acc[mi][nj][k] = 0.f;

    const int nch = K / CHK;

#pragma unroll
    for (int p = 0; p < NSTG - 1; p++) {
        const uint32_t s = sbase + (uint32_t)p * STG_B;
        const size_t ka = aoff + (size_t)p * CHK;
        const size_t kbo = boff + (size_t)p * CHK;
#pragma unroll
        for (int j = 0; j < 4; j++) {
            CP16(s + 0*TILEK + stC[j], Ah + ka + j * 8);
            CP16(s + 1*TILEK + stC[j], Bh + kbo + j * 8);
        }
        CP_COMMIT();
    }

    for (int ch = 0; ch < nch; ch++) {
        if (ch + 1 < nch) CP_WAIT1(); else CP_WAIT0();
        __syncthreads();

        if (ch + 2 < nch) {
            const uint32_t s = sbase + (uint32_t)((ch + 2) % NSTG) * STG_B;
            const size_t ka = aoff + (size_t)(ch + 2) * CHK;
            const size_t kbo = boff + (size_t)(ch + 2) * CHK;
#pragma unroll
            for (int j = 0; j < 4; j++) {
                CP16(s + 0*TILEK + stC[j], Ah + ka + j * 8);
                CP16(s + 1*TILEK + stC[j], Bh + kbo + j * 8);
            }
            CP_COMMIT();
        }

        const uint32_t bufb = sbase + (uint32_t)(ch % NSTG) * STG_B;
#pragma unroll
        for (int ks = 0; ks < 4; ks++) {
            const uint32_t koff = (uint32_t)(ks * 32 + kb);
            uint32_t ah[4][4], bh[2][4];
#pragma unroll
            for (int mi = 0; mi < 4; mi++)
                ldsm_x4(ah[mi], bufb + 0*TILEK + aRow[mi] + (koff ^ aSwz[mi]));
#pragma unroll
            for (int nj = 0; nj < 2; nj++)
                ldsm_x4(bh[nj], bufb + 1*TILEK + bRow[nj] + (koff ^ bSwz[nj]));
#pragma unroll
            for (int mi = 0; mi < 4; mi++)
#pragma unroll
                for (int nj = 0; nj < 4; nj++)
                    mma_f16(acc[mi][nj], ah[mi], bh[nj>>1][nj&1], bh[nj>>1][(nj&1)+2]);
        }
    }

    const int er = lane >> 2;
    const int ec = (lane & 3) * 2;
    if (C) {
#pragma unroll
        for (int mi = 0; mi < 4; mi++) {
            const int r0 = bm + warpM + mi * 16 + er;
#pragma unroll
            for (int nj = 0; nj < 4; nj++) {
                const int c = bn + warpN + nj * 8 + ec;
                *(float2*)&C[(size_t)r0 * N + c]       = make_float2(acc[mi][nj][0], acc[mi][nj][1]);
                *(float2*)&C[(size_t)(r0 + 8) * N + c] = make_float2(acc[mi][nj][2], acc[mi][nj][3]);
            }
        }
    } else {
#pragma unroll
        for (int mi = 0; mi < 4; mi++) {
            const int r0 = bm + warpM + mi * 16 + er;
#pragma unroll
            for (int nj = 0; nj < 4; nj++) {
                const int c = bn + warpN + nj * 8 + ec;
                *(uint32_t*)&Ch[(size_t)r0 * N + c]       = packh(acc[mi][nj][0], acc[mi][nj][1]);
                *(uint32_t*)&Ch[(size_t)(r0 + 8) * N + c] = packh(acc[mi][nj][2], acc[mi][nj][3]);
            }
        }
    }
}

// ===========================================================================
// fp16 flash attention, BQ=128, BK=64, 256 threads, 4-stage cp.async,
// 2 CTAs/SM (R11 geometry) + exp2-domain softmax (validated in R12).
// ===========================================================================
#define FA_NSTG 4
#define FA_STG  16384                    // KH 8KB + VH 8KB
#define FA_SMEM (FA_NSTG * FA_STG)       // 65536 B

__global__ __launch_bounds__(256, 2) void flash_half(
    const __half* __restrict__ qh_g, const float* __restrict__ head_w,
    __half* __restrict__ aoh)
{
    extern __shared__ char smem[];
    const uint32_t sb = smem_u32(smem);

    const int tid  = threadIdx.x;
    const int wid  = tid >> 5;
    const int lane = tid & 31;
    const int q0 = blockIdx.x * 128;
    const int h  = blockIdx.y;
    const int b  = blockIdx.z;

    float hw;
    {
        float mx = -1e30f;
#pragma unroll
        for (int i = 0; i < NHEAD; i++) mx = fmaxf(mx, head_w[i]);
        float ssum = 0.f;
#pragma unroll
        for (int i = 0; i < NHEAD; i++) ssum += __expf(head_w[i] - mx);
        hw = __expf(head_w[h] - mx) / ssum;
    }

    // ---- stage Q (fp16, 16KB), read fragments ----
    {
        const int crow = tid >> 1;
        const int chalf = tid & 1;
        const size_t qoff = (size_t)(b * SEQ + q0 + crow) * 3 * DIMC + h * HD + chalf * 32;
#pragma unroll
        for (int j = 0; j < 4; j++) {
            uint32_t off = (uint32_t)(crow * 128 + (chalf * 4 + j) * 16);
            off = off ^ ((off >> 3) & 0x70);
            CP16(sb + off, qh_g + qoff + j * 8);
        }
        CP_COMMIT();
        CP_WAIT0();
        __syncthreads();
    }

    const int lrow = lane & 15;
    const int kb   = (lane >> 4) * 16;
    uint32_t qh[4][4];
    {
        const uint32_t aOff = (uint32_t)((wid * 16 + lrow) * 128);
        const uint32_t aSwz = (uint32_t)((lrow & 7) << 4);
#pragma unroll
        for (int ks = 0; ks < 4; ks++) {
            const uint32_t koff = (uint32_t)(ks * 32 + kb);
            ldsm_x4(qh[ks], sb + aOff + (koff ^ aSwz));
        }
    }
    __syncthreads();   // Q fully read before KV staging overwrites

    const int row4 = tid >> 2;
    const int q4   = tid & 3;
    uint32_t stK[2];
#pragma unroll
    for (int j = 0; j < 2; j++) {
        uint32_t off = (uint32_t)(row4 * 128 + (q4 * 2 + j) * 16);
        stK[j] = off ^ ((off >> 3) & 0x70);
    }
    const size_t kvbase = (size_t)(b * SEQ + row4) * 3 * DIMC + h * HD + q4 * 16;
    const size_t kstep  = (size_t)64 * 3 * DIMC;

    const int ntl = SEQ / 64;

#pragma unroll
    for (int p = 0; p < FA_NSTG - 1; p++) {
        const uint32_t s = sb + (uint32_t)p * FA_STG;
        const size_t kt_ = kvbase + (size_t)p * kstep + (size_t)1 * DIMC;
        const size_t vt_ = kvbase + (size_t)p * kstep + (size_t)2 * DIMC;
#pragma unroll
        for (int j = 0; j < 2; j++) {
            CP16(s + 0*8192 + stK[j], qh_g + kt_ + j * 8);
            CP16(s + 1*8192 + stK[j], qh_g + vt_ + j * 8);
        }
        CP_COMMIT();
    }

    uint32_t bOff[4];
#pragma unroll
    for (int g = 0; g < 4; g++) bOff[g] = (uint32_t)((g * 16 + lrow) * 128);
    const uint32_t bSwz = (uint32_t)((lrow & 7) << 4);
    const uint32_t vRowBase = (uint32_t)(lane & 15);
    const uint32_t vColPart = (uint32_t)((lane >> 4) * 16);

    float m_r[2] = {-1e30f, -1e30f};     // exp2 (scaled) domain
    float l_r[2] = {0.f, 0.f};
    float o[8][4];
#pragma unroll
    for (int g = 0; g < 8; g++)
#pragma unroll
        for (int e = 0; e < 4; e++) o[g][e] = 0.f;

    for (int kt = 0; kt < ntl; kt++) {
        const int rem = ntl - 1 - kt;
        if (rem >= 2) CP_WAIT2(); else if (rem == 1) CP_WAIT1(); else CP_WAIT0();
        __syncthreads();

        if (kt + FA_NSTG - 1 < ntl) {
            const uint32_t s = sb + (uint32_t)((kt + FA_NSTG - 1) % FA_NSTG) * FA_STG;
            const size_t kt_ = kvbase + (size_t)(kt + FA_NSTG - 1) * kstep + (size_t)1 * DIMC;
            const size_t vt_ = kvbase + (size_t)(kt + FA_NSTG - 1) * kstep + (size_t)2 * DIMC;
#pragma unroll
            for (int j = 0; j < 2; j++) {
                CP16(s + 0*8192 + stK[j], qh_g + kt_ + j * 8);
                CP16(s + 1*8192 + stK[j], qh_g + vt_ + j * 8);
            }
            CP_COMMIT();
        }

        const uint32_t sKH = sb + (uint32_t)(kt % FA_NSTG) * FA_STG;
        const uint32_t sVH = sKH + 8192;

        // ---- S = Q K^T (fp16) ----
        float s[8][4];
#pragma unroll
        for (int nj = 0; nj < 8; nj++)
#pragma unroll
            for (int e = 0; e < 4; e++) s[nj][e] = 0.f;

#pragma unroll
        for (int ks = 0; ks < 4; ks++) {
            const uint32_t koff = (uint32_t)(ks * 32 + kb);
#pragma unroll
            for (int g = 0; g < 4; g++) {
                uint32_t kh4[4];
                ldsm_x4(kh4, sKH + bOff[g] + (koff ^ bSwz));
                mma_f16(s[2*g],   qh[ks], kh4[0], kh4[2]);
                mma_f16(s[2*g+1], qh[ks], kh4[1], kh4[3]);
            }
        }

        // ---- online softmax (exp2 domain: s scaled by SCALE*log2e) ----
        float mx0 = -1e30f, mx1 = -1e30f;
#pragma unroll
        for (int nj = 0; nj < 8; nj++) {
            s[nj][0] *= SC2; s[nj][1] *= SC2; s[nj][2] *= SC2; s[nj][3] *= SC2;
            mx0 = fmaxf(mx0, fmaxf(s[nj][0], s[nj][1]));
            mx1 = fmaxf(mx1, fmaxf(s[nj][2], s[nj][3]));
        }
        mx0 = fmaxf(mx0, __shfl_xor_sync(0xffffffffu, mx0, 1));
        mx0 = fmaxf(mx0, __shfl_xor_sync(0xffffffffu, mx0, 2));
        mx1 = fmaxf(mx1, __shfl_xor_sync(0xffffffffu, mx1, 1));
        mx1 = fmaxf(mx1, __shfl_xor_sync(0xffffffffu, mx1, 2));
        const float mn0 = fmaxf(m_r[0], mx0);
        const float mn1 = fmaxf(m_r[1], mx1);
        const float alpha0 = exp2f(m_r[0] - mn0);
        const float alpha1 = exp2f(m_r[1] - mn1);
        m_r[0] = mn0; m_r[1] = mn1;
        float sum0 = 0.f, sum1 = 0.f;
#pragma unroll
        for (int nj = 0; nj < 8; nj++) {
            s[nj][0] = exp2f(s[nj][0] - mn0); sum0 += s[nj][0];
            s[nj][1] = exp2f(s[nj][1] - mn0); sum0 += s[nj][1];
            s[nj][2] = exp2f(s[nj][2] - mn1); sum1 += s[nj][2];
            s[nj][3] = exp2f(s[nj][3] - mn1); sum1 += s[nj][3];
        }
        sum0 += __shfl_xor_sync(0xffffffffu, sum0, 1);
        sum0 += __shfl_xor_sync(0xffffffffu, sum0, 2);
        sum1 += __shfl_xor_sync(0xffffffffu, sum1, 1);
        sum1 += __shfl_xor_sync(0xffffffffu, sum1, 2);
        l_r[0] = l_r[0] * alpha0 + sum0;
        l_r[1] = l_r[1] * alpha1 + sum1;
#pragma unroll
        for (int g = 0; g < 8; g++) {
            o[g][0] *= alpha0; o[g][1] *= alpha0;
            o[g][2] *= alpha1; o[g][3] *= alpha1;
        }

        // ---- P fragments (fp16) ----
        uint32_t pa[4][4];
#pragma unroll
        for (int t = 0; t < 4; t++) {
            pa[t][0] = packh(s[2*t][0], s[2*t][1]);
            pa[t][1] = packh(s[2*t][2], s[2*t][3]);
            pa[t][2] = packh(s[2*t+1][0], s[2*t+1][1]);
            pa[t][3] = packh(s[2*t+1][2], s[2*t+1][3]);
        }

        // ---- O += P V (fp16) ----
#pragma unroll
        for (int t = 0; t < 4; t++) {
#pragma unroll
            for (int g = 0; g < 4; g++) {
                const uint32_t vr = (uint32_t)(16 * t) + vRowBase;
                const uint32_t vc = (uint32_t)(g * 32) + vColPart;
                const uint32_t voff = vr * 128 + (vc ^ ((vr & 7) << 4));
                uint32_t vh4[4];
                ldsm_x4_t(vh4, sVH + voff);
                mma_f16(o[2*g],   pa[t], vh4[0], vh4[1]);
                mma_f16(o[2*g+1], pa[t], vh4[2], vh4[3]);
            }
        }
    }

    // ---- epilogue: O/l * hw -> fp16 ao ----
    const int er = lane >> 2;
    const int ec = (lane & 3) * 2;
    const float inv0 = hw / l_r[0];
    const float inv1 = hw / l_r[1];
    const int r0 = q0 + wid * 16 + er;
#pragma unroll
    for (int g = 0; g < 8; g++) {
        const int d = h * HD + g * 8 + ec;
        const size_t i0 = (size_t)(b * SEQ + r0) * DIMC + d;
        const size_t i1 = (size_t)(b * SEQ + r0 + 8) * DIMC + d;
        *(uint32_t*)&aoh[i0] = packh(o[g][0] * inv0, o[g][1] * inv0);
        *(uint32_t*)&aoh[i1] = packh(o[g][2] * inv1, o[g][3] * inv1);
    }
}

// ===========================================================================
extern "C" void kernel_launch(void* const* d_in, const int* in_sizes, int n_in,
                              void* d_out, int out_size)
{
    const float* x      = (const float*)d_in[0];
    const float* w_qkv  = (const float*)d_in[1];
    const float* w_proj = (const float*)d_in[2];
    const float* head_w = (const float*)d_in[3];
    float* out = (float*)d_out;

    __half *xh, *wqh, *wph, *qh, *aoh;
    cudaGetSymbolAddress((void**)&xh,  g_xh);
    cudaGetSymbolAddress((void**)&wqh, g_wqh);
    cudaGetSymbolAddress((void**)&wph, g_wph);
    cudaGetSymbolAddress((void**)&qh,  g_qh);
    cudaGetSymbolAddress((void**)&aoh, g_aoh);

    cudaFuncSetAttribute(gemm_half, cudaFuncAttributeMaxDynamicSharedMemorySize, GEMM_SMEM);
    cudaFuncSetAttribute(flash_half, cudaFuncAttributeMaxDynamicSharedMemorySize, FA_SMEM);

    // 0) fused convert prepass (x, w_qkv, w_proj -> fp16) in ONE launch
    {
        dim3 g0((M_TOT * DIMC) / 1024, 3);
        cvt16_all<<<g0, 256>>>(x, xh, w_qkv, wqh, w_proj, wph);
    }

    // 1) QKV projection -> fp16 qkv
    dim3 g1(QKV_N / 128, M_TOT / 128);
    gemm_half<<<g1, 256, GEMM_SMEM>>>(xh, wqh, nullptr, qh, M_TOT, QKV_N, DIMC);

    // 2) flash attention + head weights -> fp16 ao  (BQ=128, 256 thr, 2 CTAs/SM)
    dim3 g2(SEQ / 128, NHEAD, BATCH);
    flash_half<<<g2, 256, FA_SMEM>>>(qh, head_w, aoh);

    // 3) output projection -> fp32 out
    dim3 g3(DIMC / 128, M_TOT / 128);
    gemm_half<<<g3, 256, GEMM_SMEM>>>(aoh, wph, out, nullptr, M_TOT, DIMC, DIMC);
}

// round 14
// speedup vs baseline: 1.0823x; 1.0434x over previous
#include <cuda_runtime.h>
#include <cuda_fp16.h>
#include <cstdint>

#define BATCH 2
#define SEQ   2048
#define DIMC  1024
#define NHEAD 16
#define HD    64
#define SCALE 0.125f            // 64^-0.5
#define SC2   (0.125f * 1.44269504089f)   // SCALE * log2(e)

#define M_TOT (BATCH*SEQ)       // 4096
#define QKV_N (3*DIMC)          // 3072

// fp16 scratch (allocation-free rule: __device__ globals)
__device__ __half g_xh [(size_t)M_TOT * DIMC];
__device__ __half g_wqh[(size_t)QKV_N * DIMC];
__device__ __half g_wph[(size_t)DIMC * DIMC];
__device__ __half g_qh [(size_t)M_TOT * QKV_N];
__device__ __half g_aoh[(size_t)M_TOT * DIMC];

// ===========================================================================
// Primitives
// ===========================================================================
__device__ __forceinline__ uint32_t smem_u32(const void* p) {
    uint32_t a;
    asm("{ .reg .u64 t; cvta.to.shared.u64 t, %1; cvt.u32.u64 %0, t; }" : "=r"(a) : "l"(p));
    return a;
}
__device__ __forceinline__ void ldsm_x4(uint32_t* r, uint32_t addr) {
    asm volatile("ldmatrix.sync.aligned.m8n8.x4.shared.b16 {%0,%1,%2,%3}, [%4];"
        : "=r"(r[0]), "=r"(r[1]), "=r"(r[2]), "=r"(r[3]) : "r"(addr));
}
__device__ __forceinline__ void ldsm_x4_t(uint32_t* r, uint32_t addr) {
    asm volatile("ldmatrix.sync.aligned.m8n8.x4.trans.shared.b16 {%0,%1,%2,%3}, [%4];"
        : "=r"(r[0]), "=r"(r[1]), "=r"(r[2]), "=r"(r[3]) : "r"(addr));
}
// D(16x8 f32) += A(16x16 f16) * B(16x8 f16, col)
__device__ __forceinline__ void mma_f16(float* d, const uint32_t* a, uint32_t b0, uint32_t b1) {
    asm volatile(
        "mma.sync.aligned.m16n8k16.row.col.f32.f16.f16.f32 "
        "{%0,%1,%2,%3}, {%4,%5,%6,%7}, {%8,%9}, {%0,%1,%2,%3};"
        : "+f"(d[0]), "+f"(d[1]), "+f"(d[2]), "+f"(d[3])
        : "r"(a[0]), "r"(a[1]), "r"(a[2]), "r"(a[3]), "r"(b0), "r"(b1));
}
__device__ __forceinline__ uint32_t packh(float lo, float hi) {
    __half2 t = __floats2half2_rn(lo, hi);
    return *reinterpret_cast<uint32_t*>(&t);
}
#define CP16(dst, src) \
    asm volatile("cp.async.cg.shared.global [%0], [%1], 16;" \
        :: "r"(dst), "l"(__cvta_generic_to_global(src)) : "memory")
#define CP_COMMIT() asm volatile("cp.async.commit_group;" ::: "memory")
#define CP_WAIT0()  asm volatile("cp.async.wait_group 0;" ::: "memory")
#define CP_WAIT1()  asm volatile("cp.async.wait_group 1;" ::: "memory")
#define CP_WAIT2()  asm volatile("cp.async.wait_group 2;" ::: "memory")

// ===========================================================================
// Fused convert prepass: fp32 -> fp16 over 3 segments (one launch)
// ===========================================================================
__global__ __launch_bounds__(256) void cvt16_all(
    const float* __restrict__ x,  __half* __restrict__ xh,
    const float* __restrict__ wq, __half* __restrict__ wqh,
    const float* __restrict__ wp, __half* __restrict__ wph)
{
    const float* in;  __half* out;  int n;
    if (blockIdx.y == 0)      { in = x;  out = xh;  n = M_TOT * DIMC; }
    else if (blockIdx.y == 1) { in = wq; out = wqh; n = QKV_N * DIMC; }
    else                      { in = wp; out = wph; n = DIMC * DIMC; }
    int i = (blockIdx.x * 256 + threadIdx.x) * 4;
    if (i >= n) return;
    float4 v = *(const float4*)(in + i);
    *(uint2*)(out + i) = make_uint2(packh(v.x, v.y), packh(v.z, v.w));
}

// ===========================================================================
// fp16 GEMM-NT, 256x128 CTA tile, 512 threads (16 warps), 1 CTA/SM,
// cp.async 3-stage pipeline, K-chunk 64. Warp tile 64x32 (unchanged inner).
// ===========================================================================
#define CHK    64
#define A_BYT  32768                     // 256 rows x 128 bytes
#define B_BYT  16384                     // 128 rows x 128 bytes
#define STG_B  (A_BYT + B_BYT)           // 48KB
#define NSTG   3
#define GEMM_SMEM (NSTG * STG_B)         // 147456 B

__global__ __launch_bounds__(512, 1) void gemm_half(
    const __half* __restrict__ Ah, const __half* __restrict__ Bh,
    float* __restrict__ C, __half* __restrict__ Ch,
    int M, int N, int K)
{
    extern __shared__ char smem[];
    const uint32_t sbase = smem_u32(smem);
    const int tid  = threadIdx.x;
    const int wid  = tid >> 5;           // 0..15
    const int lane = tid & 31;
    const int bm = blockIdx.y * 256;
    const int bn = blockIdx.x * 128;

    const int warpM = (wid & 3) * 64;    // 4 M-groups of 64
    const int warpN = (wid >> 2) * 32;   // 4 N-groups of 32
    const int lrow = lane & 15;
    const int kb   = (lane >> 4) * 16;

    uint32_t aRow[4], aSwz[4];
#pragma unroll
    for (int mi = 0; mi < 4; mi++) {
        int r = warpM + mi * 16 + lrow;
        aRow[mi] = (uint32_t)(r * 128);
        aSwz[mi] = (uint32_t)((r & 7) << 4);
    }
    uint32_t bRow[2], bSwz[2];
#pragma unroll
    for (int nj = 0; nj < 2; nj++) {
        int r = warpN + nj * 16 + lrow;
        bRow[nj] = (uint32_t)(r * 128);
        bSwz[nj] = (uint32_t)((r & 7) << 4);
    }

    // A staging: 512 thr, 256 rows: row=tid>>1, half=tid&1, 4 chunks
    const int arow = tid >> 1;
    const int ahalf = tid & 1;
    uint32_t stA[4];
#pragma unroll
    for (int j = 0; j < 4; j++) {
        uint32_t off = (uint32_t)(arow * 128 + (ahalf * 4 + j) * 16);
        stA[j] = off ^ ((off >> 3) & 0x70);
    }
    const size_t aoff = (size_t)(bm + arow) * K + ahalf * 32;

    // B staging: 128 rows: row=tid>>2, quarter=tid&3, 2 chunks
    const int brow = tid >> 2;
    const int bq   = tid & 3;
    uint32_t stB[2];
#pragma unroll
    for (int j = 0; j < 2; j++) {
        uint32_t off = (uint32_t)(brow * 128 + (bq * 2 + j) * 16);
        stB[j] = off ^ ((off >> 3) & 0x70);
    }
    const size_t boff = (size_t)(bn + brow) * K + bq * 16;

    float acc[4][4][4];
#pragma unroll
    for (int mi = 0; mi < 4; mi++)
#pragma unroll
        for (int nj = 0; nj < 4; nj++)
#pragma unroll
            for (int k = 0; k < 4; k++) acc[mi][nj][k] = 0.f;

    const int nch = K / CHK;             // 16 for K=1024

#pragma unroll
    for (int p = 0; p < NSTG - 1; p++) {
        const uint32_t s = sbase + (uint32_t)p * STG_B;
        const size_t ka = aoff + (size_t)p * CHK;
        const size_t kbo = boff + (size_t)p * CHK;
#pragma unroll
        for (int j = 0; j < 4; j++)
            CP16(s + stA[j], Ah + ka + j * 8);
#pragma unroll
        for (int j = 0; j < 2; j++)
            CP16(s + A_BYT + stB[j], Bh + kbo + j * 8);
        CP_COMMIT();
    }

    for (int ch = 0; ch < nch; ch++) {
        if (ch + 1 < nch) CP_WAIT1(); else CP_WAIT0();
        __syncthreads();

        if (ch + 2 < nch) {
            const uint32_t s = sbase + (uint32_t)((ch + 2) % NSTG) * STG_B;
            const size_t ka = aoff + (size_t)(ch + 2) * CHK;
            const size_t kbo = boff + (size_t)(ch + 2) * CHK;
#pragma unroll
            for (int j = 0; j < 4; j++)
                CP16(s + stA[j], Ah + ka + j * 8);
#pragma unroll
            for (int j = 0; j < 2; j++)
                CP16(s + A_BYT + stB[j], Bh + kbo + j * 8);
            CP_COMMIT();
        }

        const uint32_t bufb = sbase + (uint32_t)(ch % NSTG) * STG_B;
#pragma unroll
        for (int ks = 0; ks < 4; ks++) {
            const uint32_t koff = (uint32_t)(ks * 32 + kb);
            uint32_t ah[4][4], bh[2][4];
#pragma unroll
            for (int mi = 0; mi < 4; mi++)
                ldsm_x4(ah[mi], bufb + aRow[mi] + (koff ^ aSwz[mi]));
#pragma unroll
            for (int nj = 0; nj < 2; nj++)
                ldsm_x4(bh[nj], bufb + A_BYT + bRow[nj] + (koff ^ bSwz[nj]));
#pragma unroll
            for (int mi = 0; mi < 4; mi++)
#pragma unroll
                for (int nj = 0; nj < 4; nj++)
                    mma_f16(acc[mi][nj], ah[mi], bh[nj>>1][nj&1], bh[nj>>1][(nj&1)+2]);
        }
    }

    const int er = lane >> 2;
    const int ec = (lane & 3) * 2;
    if (C) {
#pragma unroll
        for (int mi = 0; mi < 4; mi++) {
            const int r0 = bm + warpM + mi * 16 + er;
#pragma unroll
            for (int nj = 0; nj < 4; nj++) {
                const int c = bn + warpN + nj * 8 + ec;
                *(float2*)&C[(size_t)r0 * N + c]       = make_float2(acc[mi][nj][0], acc[mi][nj][1]);
                *(float2*)&C[(size_t)(r0 + 8) * N + c] = make_float2(acc[mi][nj][2], acc[mi][nj][3]);
            }
        }
    } else {
#pragma unroll
        for (int mi = 0; mi < 4; mi++) {
            const int r0 = bm + warpM + mi * 16 + er;
#pragma unroll
            for (int nj = 0; nj < 4; nj++) {
                const int c = bn + warpN + nj * 8 + ec;
                *(uint32_t*)&Ch[(size_t)r0 * N + c]       = packh(acc[mi][nj][0], acc[mi][nj][1]);
                *(uint32_t*)&Ch[(size_t)(r0 + 8) * N + c] = packh(acc[mi][nj][2], acc[mi][nj][3]);
            }
        }
    }
}

// ===========================================================================
// fp16 flash attention, BQ=128, BK=64, 256 threads, 4-stage cp.async,
// 2 CTAs/SM, exp2-domain softmax. (unchanged from R13 passing kernel)
// ===========================================================================
#define FA_NSTG 4
#define FA_STG  16384                    // KH 8KB + VH 8KB
#define FA_SMEM (FA_NSTG * FA_STG)       // 65536 B

__global__ __launch_bounds__(256, 2) void flash_half(
    const __half* __restrict__ qh_g, const float* __restrict__ head_w,
    __half* __restrict__ aoh)
{
    extern __shared__ char smem[];
    const uint32_t sb = smem_u32(smem);

    const int tid  = threadIdx.x;
    const int wid  = tid >> 5;
    const int lane = tid & 31;
    const int q0 = blockIdx.x * 128;
    const int h  = blockIdx.y;
    const int b  = blockIdx.z;

    float hw;
    {
        float mx = -1e30f;
#pragma unroll
        for (int i = 0; i < NHEAD; i++) mx = fmaxf(mx, head_w[i]);
        float ssum = 0.f;
#pragma unroll
        for (int i = 0; i < NHEAD; i++) ssum += __expf(head_w[i] - mx);
        hw = __expf(head_w[h] - mx) / ssum;
    }

    // ---- stage Q (fp16, 16KB), read fragments ----
    {
        const int crow = tid >> 1;
        const int chalf = tid & 1;
        const size_t qoff = (size_t)(b * SEQ + q0 + crow) * 3 * DIMC + h * HD + chalf * 32;
#pragma unroll
        for (int j = 0; j < 4; j++) {
            uint32_t off = (uint32_t)(crow * 128 + (chalf * 4 + j) * 16);
            off = off ^ ((off >> 3) & 0x70);
            CP16(sb + off, qh_g + qoff + j * 8);
        }
        CP_COMMIT();
        CP_WAIT0();
        __syncthreads();
    }

    const int lrow = lane & 15;
    const int kb   = (lane >> 4) * 16;
    uint32_t qh[4][4];
    {
        const uint32_t aOff = (uint32_t)((wid * 16 + lrow) * 128);
        const uint32_t aSwz = (uint32_t)((lrow & 7) << 4);
#pragma unroll
        for (int ks = 0; ks < 4; ks++) {
            const uint32_t koff = (uint32_t)(ks * 32 + kb);
            ldsm_x4(qh[ks], sb + aOff + (koff ^ aSwz));
        }
    }
    __syncthreads();   // Q fully read before KV staging overwrites

    const int row4 = tid >> 2;
    const int q4   = tid & 3;
    uint32_t stK[2];
#pragma unroll
    for (int j = 0; j < 2; j++) {
        uint32_t off = (uint32_t)(row4 * 128 + (q4 * 2 + j) * 16);
        stK[j] = off ^ ((off >> 3) & 0x70);
    }
    const size_t kvbase = (size_t)(b * SEQ + row4) * 3 * DIMC + h * HD + q4 * 16;
    const size_t kstep  = (size_t)64 * 3 * DIMC;

    const int ntl = SEQ / 64;

#pragma unroll
    for (int p = 0; p < FA_NSTG - 1; p++) {
        const uint32_t s = sb + (uint32_t)p * FA_STG;
        const size_t kt_ = kvbase + (size_t)p * kstep + (size_t)1 * DIMC;
        const size_t vt_ = kvbase + (size_t)p * kstep + (size_t)2 * DIMC;
#pragma unroll
        for (int j = 0; j < 2; j++) {
            CP16(s + 0*8192 + stK[j], qh_g + kt_ + j * 8);
            CP16(s + 1*8192 + stK[j], qh_g + vt_ + j * 8);
        }
        CP_COMMIT();
    }

    uint32_t bOff[4];
#pragma unroll
    for (int g = 0; g < 4; g++) bOff[g] = (uint32_t)((g * 16 + lrow) * 128);
    const uint32_t bSwz = (uint32_t)((lrow & 7) << 4);
    const uint32_t vRowBase = (uint32_t)(lane & 15);
    const uint32_t vColPart = (uint32_t)((lane >> 4) * 16);

    float m_r[2] = {-1e30f, -1e30f};     // exp2 (scaled) domain
    float l_r[2] = {0.f, 0.f};
    float o[8][4];
#pragma unroll
    for (int g = 0; g < 8; g++)
#pragma unroll
        for (int e = 0; e < 4; e++) o[g][e] = 0.f;

    for (int kt = 0; kt < ntl; kt++) {
        const int rem = ntl - 1 - kt;
        if (rem >= 2) CP_WAIT2(); else if (rem == 1) CP_WAIT1(); else CP_WAIT0();
        __syncthreads();

        if (kt + FA_NSTG - 1 < ntl) {
            const uint32_t s = sb + (uint32_t)((kt + FA_NSTG - 1) % FA_NSTG) * FA_STG;
            const size_t kt_ = kvbase + (size_t)(kt + FA_NSTG - 1) * kstep + (size_t)1 * DIMC;
            const size_t vt_ = kvbase + (size_t)(kt + FA_NSTG - 1) * kstep + (size_t)2 * DIMC;
#pragma unroll
            for (int j = 0; j < 2; j++) {
                CP16(s + 0*8192 + stK[j], qh_g + kt_ + j * 8);
                CP16(s + 1*8192 + stK[j], qh_g + vt_ + j * 8);
            }
            CP_COMMIT();
        }

        const uint32_t sKH = sb + (uint32_t)(kt % FA_NSTG) * FA_STG;
        const uint32_t sVH = sKH + 8192;

        // ---- S = Q K^T (fp16) ----
        float s[8][4];
#pragma unroll
        for (int nj = 0; nj < 8; nj++)
#pragma unroll
            for (int e = 0; e < 4; e++) s[nj][e] = 0.f;

#pragma unroll
        for (int ks = 0; ks < 4; ks++) {
            const uint32_t koff = (uint32_t)(ks * 32 + kb);
#pragma unroll
            for (int g = 0; g < 4; g++) {
                uint32_t kh4[4];
                ldsm_x4(kh4, sKH + bOff[g] + (koff ^ bSwz));
                mma_f16(s[2*g],   qh[ks], kh4[0], kh4[2]);
                mma_f16(s[2*g+1], qh[ks], kh4[1], kh4[3]);
            }
        }

        // ---- online softmax (exp2 domain) ----
        float mx0 = -1e30f, mx1 = -1e30f;
#pragma unroll
        for (int nj = 0; nj < 8; nj++) {
            s[nj][0] *= SC2; s[nj][1] *= SC2; s[nj][2] *= SC2; s[nj][3] *= SC2;
            mx0 = fmaxf(mx0, fmaxf(s[nj][0], s[nj][1]));
            mx1 = fmaxf(mx1, fmaxf(s[nj][2], s[nj][3]));
        }
        mx0 = fmaxf(mx0, __shfl_xor_sync(0xffffffffu, mx0, 1));
        mx0 = fmaxf(mx0, __shfl_xor_sync(0xffffffffu, mx0, 2));
        mx1 = fmaxf(mx1, __shfl_xor_sync(0xffffffffu, mx1, 1));
        mx1 = fmaxf(mx1, __shfl_xor_sync(0xffffffffu, mx1, 2));
        const float mn0 = fmaxf(m_r[0], mx0);
        const float mn1 = fmaxf(m_r[1], mx1);
        const float alpha0 = exp2f(m_r[0] - mn0);
        const float alpha1 = exp2f(m_r[1] - mn1);
        m_r[0] = mn0; m_r[1] = mn1;
        float sum0 = 0.f, sum1 = 0.f;
#pragma unroll
        for (int nj = 0; nj < 8; nj++) {
            s[nj][0] = exp2f(s[nj][0] - mn0); sum0 += s[nj][0];
            s[nj][1] = exp2f(s[nj][1] - mn0); sum0 += s[nj][1];
            s[nj][2] = exp2f(s[nj][2] - mn1); sum1 += s[nj][2];
            s[nj][3] = exp2f(s[nj][3] - mn1); sum1 += s[nj][3];
        }
        sum0 += __shfl_xor_sync(0xffffffffu, sum0, 1);
        sum0 += __shfl_xor_sync(0xffffffffu, sum0, 2);
        sum1 += __shfl_xor_sync(0xffffffffu, sum1, 1);
        sum1 += __shfl_xor_sync(0xffffffffu, sum1, 2);
        l_r[0] = l_r[0] * alpha0 + sum0;
        l_r[1] = l_r[1] * alpha1 + sum1;
#pragma unroll
        for (int g = 0; g < 8; g++) {
            o[g][0] *= alpha0; o[g][1] *= alpha0;
            o[g][2] *= alpha1; o[g][3] *= alpha1;
        }

        // ---- P fragments (fp16) ----
        uint32_t pa[4][4];
#pragma unroll
        for (int t = 0; t < 4; t++) {
            pa[t][0] = packh(s[2*t][0], s[2*t][1]);
            pa[t][1] = packh(s[2*t][2], s[2*t][3]);
            pa[t][2] = packh(s[2*t+1][0], s[2*t+1][1]);
            pa[t][3] = packh(s[2*t+1][2], s[2*t+1][3]);
        }

        // ---- O += P V (fp16) ----
#pragma unroll
        for (int t = 0; t < 4; t++) {
#pragma unroll
            for (int g = 0; g < 4; g++) {
                const uint32_t vr = (uint32_t)(16 * t) + vRowBase;
                const uint32_t vc = (uint32_t)(g * 32) + vColPart;
                const uint32_t voff = vr * 128 + (vc ^ ((vr & 7) << 4));
                uint32_t vh4[4];
                ldsm_x4_t(vh4, sVH + voff);
                mma_f16(o[2*g],   pa[t], vh4[0], vh4[1]);
                mma_f16(o[2*g+1], pa[t], vh4[2], vh4[3]);
            }
        }
    }

    // ---- epilogue: O/l * hw -> fp16 ao ----
    const int er = lane >> 2;
    const int ec = (lane & 3) * 2;
    const float inv0 = hw / l_r[0];
    const float inv1 = hw / l_r[1];
    const int r0 = q0 + wid * 16 + er;
#pragma unroll
    for (int g = 0; g < 8; g++) {
        const int d = h * HD + g * 8 + ec;
        const size_t i0 = (size_t)(b * SEQ + r0) * DIMC + d;
        const size_t i1 = (size_t)(b * SEQ + r0 + 8) * DIMC + d;
        *(uint32_t*)&aoh[i0] = packh(o[g][0] * inv0, o[g][1] * inv0);
        *(uint32_t*)&aoh[i1] = packh(o[g][2] * inv1, o[g][3] * inv1);
    }
}

// ===========================================================================
extern "C" void kernel_launch(void* const* d_in, const int* in_sizes, int n_in,
                              void* d_out, int out_size)
{
    const float* x      = (const float*)d_in[0];
    const float* w_qkv  = (const float*)d_in[1];
    const float* w_proj = (const float*)d_in[2];
    const float* head_w = (const float*)d_in[3];
    float* out = (float*)d_out;

    __half *xh, *wqh, *wph, *qh, *aoh;
    cudaGetSymbolAddress((void**)&xh,  g_xh);
    cudaGetSymbolAddress((void**)&wqh, g_wqh);
    cudaGetSymbolAddress((void**)&wph, g_wph);
    cudaGetSymbolAddress((void**)&qh,  g_qh);
    cudaGetSymbolAddress((void**)&aoh, g_aoh);

    cudaFuncSetAttribute(gemm_half, cudaFuncAttributeMaxDynamicSharedMemorySize, GEMM_SMEM);
    cudaFuncSetAttribute(flash_half, cudaFuncAttributeMaxDynamicSharedMemorySize, FA_SMEM);

    // 0) fused convert prepass (x, w_qkv, w_proj -> fp16) in ONE launch
    {
        dim3 g0((M_TOT * DIMC) / 1024, 3);
        cvt16_all<<<g0, 256>>>(x, xh, w_qkv, wqh, w_proj, wph);
    }

    // 1) QKV projection -> fp16 qkv   (256x128 tiles, 512 thr)
    dim3 g1(QKV_N / 128, M_TOT / 256);
    gemm_half<<<g1, 512, GEMM_SMEM>>>(xh, wqh, nullptr, qh, M_TOT, QKV_N, DIMC);

    // 2) flash attention + head weights -> fp16 ao  (BQ=128, 256 thr, 2 CTAs/SM)
    dim3 g2(SEQ / 128, NHEAD, BATCH);
    flash_half<<<g2, 256, FA_SMEM>>>(qh, head_w, aoh);

    // 3) output projection -> fp32 out   (256x128 tiles, 512 thr)
    dim3 g3(DIMC / 128, M_TOT / 256);
    gemm_half<<<g3, 512, GEMM_SMEM>>>(aoh, wph, out, nullptr, M_TOT, DIMC, DIMC);
}